// round 7
// baseline (speedup 1.0000x reference)
#include <cuda_runtime.h>
#include <cstdint>

#define HW (1024 * 1024)
#define N4 (HW / 4)                   // 262144 float4 per plane
#define NB 16
#define BPB 37
#define NBLOCKS (NB * BPB)            // 592 = 148 SMs * 4 CTAs
#define THREADS 256
#define NSTAGE 4
#define CHUNK 256                     // float4 per stream per stage (= THREADS)
#define STREAM_BYTES (CHUNK * 16)     // 4096
#define STAGE_BYTES (3 * STREAM_BYTES)// 12288
#define SMEM_BUF_OFF 128
#define SMEM_TOTAL (SMEM_BUF_OFF + NSTAGE * STAGE_BYTES)  // 49280
#define EPS 1e-6f

// per-block partial sums: {S_p, S_pp, S_tp, S_t}
__device__ float4 g_partials[NBLOCKS];
__device__ unsigned int g_count = 0;   // self-resetting

__device__ __forceinline__ uint32_t smem_u32(const void* p) {
    uint32_t a;
    asm("{ .reg .u64 t; cvta.to.shared.u64 t, %1; cvt.u32.u64 %0, t; }" : "=r"(a) : "l"(p));
    return a;
}
__device__ __forceinline__ void mbar_init(uint32_t addr, uint32_t cnt) {
    asm volatile("mbarrier.init.shared.b64 [%0], %1;" :: "r"(addr), "r"(cnt) : "memory");
}
__device__ __forceinline__ void mbar_expect_tx(uint32_t addr, uint32_t bytes) {
    asm volatile("mbarrier.arrive.expect_tx.shared.b64 _, [%0], %1;" :: "r"(addr), "r"(bytes) : "memory");
}
__device__ __forceinline__ void mbar_wait(uint32_t addr, uint32_t parity) {
    asm volatile(
        "{\n\t.reg .pred P;\n\t"
        "WL%=:\n\t"
        "mbarrier.try_wait.parity.acquire.cta.shared::cta.b64 P, [%0], %1, 0x989680;\n\t"
        "@!P bra WL%=;\n\t}"
        :: "r"(addr), "r"(parity) : "memory");
}
__device__ __forceinline__ void bulk_g2s(uint32_t dst, const void* src, uint32_t bytes, uint32_t mbar) {
    asm volatile(
        "cp.async.bulk.shared::cta.global.mbarrier::complete_tx::bytes [%0], [%1], %2, [%3];"
        :: "r"(dst), "l"(src), "r"(bytes), "r"(mbar) : "memory");
}

__device__ __forceinline__ void accum(float l0, float l1, int t,
                                      float& sp, float& spp, float& stp, float& st) {
    float e = __expf(l0 - l1);
    float p = __fdividef(1.0f, 1.0f + e);
    float tf = (t != 0) ? 1.0f : 0.0f;
    sp  += p;
    spp += p * p;
    stp += tf * p;
    st  += tf;
}

__global__ __launch_bounds__(THREADS)
void dice_tma_kernel(const float* __restrict__ logits,
                     const int* __restrict__ labels,
                     float* __restrict__ out) {
    extern __shared__ __align__(128) char smem[];
    const uint32_t smem_base = smem_u32(smem);
    const uint32_t mbar_base = smem_base;                 // full[s] at +8*s
    const uint32_t buf_base  = smem_base + SMEM_BUF_OFF;

    const int b   = blockIdx.x / BPB;
    const int blk = blockIdx.x % BPB;

    const char* l0p = (const char*)(logits + (size_t)b * 2 * HW);
    const char* l1p = (const char*)(logits + (size_t)b * 2 * HW + HW);
    const char* tp  = (const char*)(labels + (size_t)b * HW);

    // balanced split of N4 float4s over BPB blocks
    const int start = (int)(((long long)blk       * N4) / BPB);
    const int end   = (int)(((long long)(blk + 1) * N4) / BPB);
    const int n     = end - start;
    const int nstages = (n + CHUNK - 1) / CHUNK;

    l0p += (size_t)start * 16;
    l1p += (size_t)start * 16;
    tp  += (size_t)start * 16;

    const int tid = threadIdx.x;

    if (tid == 0) {
#pragma unroll
        for (int s = 0; s < NSTAGE; s++) mbar_init(mbar_base + 8u * s, 1);
        asm volatile("fence.proxy.async.shared::cta;" ::: "memory");
    }
    __syncthreads();

    // prologue: fill the pipeline
    if (tid == 0) {
#pragma unroll
        for (int s = 0; s < NSTAGE; s++) {
            if (s < nstages) {
                const int off = s * CHUNK;
                int rem = n - off; if (rem > CHUNK) rem = CHUNK;
                const uint32_t bytes = (uint32_t)rem * 16u;
                const uint32_t fb = mbar_base + 8u * s;
                mbar_expect_tx(fb, bytes * 3u);
                const uint32_t d = buf_base + (uint32_t)s * STAGE_BYTES;
                bulk_g2s(d,                    l0p + (size_t)off * 16, bytes, fb);
                bulk_g2s(d + STREAM_BYTES,     l1p + (size_t)off * 16, bytes, fb);
                bulk_g2s(d + 2 * STREAM_BYTES, tp  + (size_t)off * 16, bytes, fb);
            }
        }
    }

    float sp = 0.f, spp = 0.f, stp = 0.f, st = 0.f;

    for (int k = 0; k < nstages; k++) {
        const int slot = k % NSTAGE;
        mbar_wait(mbar_base + 8u * slot, (uint32_t)((k / NSTAGE) & 1));

        int rem = n - k * CHUNK; if (rem > CHUNK) rem = CHUNK;
        if (tid < rem) {
            const char* d = smem + SMEM_BUF_OFF + slot * STAGE_BYTES + tid * 16;
            float4 a = *(const float4*)(d);
            float4 c = *(const float4*)(d + STREAM_BYTES);
            int4   t = *(const int4*)(d + 2 * STREAM_BYTES);
            accum(a.x, c.x, t.x, sp, spp, stp, st);
            accum(a.y, c.y, t.y, sp, spp, stp, st);
            accum(a.z, c.z, t.z, sp, spp, stp, st);
            accum(a.w, c.w, t.w, sp, spp, stp, st);
        }
        __syncthreads();   // all consumed -> slot reusable

        if (tid == 0) {
            const int s2 = k + NSTAGE;
            if (s2 < nstages) {
                const int off = s2 * CHUNK;
                int r2 = n - off; if (r2 > CHUNK) r2 = CHUNK;
                const uint32_t bytes = (uint32_t)r2 * 16u;
                const uint32_t fb = mbar_base + 8u * slot;
                mbar_expect_tx(fb, bytes * 3u);
                const uint32_t d = buf_base + (uint32_t)slot * STAGE_BYTES;
                bulk_g2s(d,                    l0p + (size_t)off * 16, bytes, fb);
                bulk_g2s(d + STREAM_BYTES,     l1p + (size_t)off * 16, bytes, fb);
                bulk_g2s(d + 2 * STREAM_BYTES, tp  + (size_t)off * 16, bytes, fb);
            }
        }
    }

    // block reduce to one float4
#pragma unroll
    for (int o = 16; o > 0; o >>= 1) {
        sp  += __shfl_down_sync(0xFFFFFFFFu, sp, o);
        spp += __shfl_down_sync(0xFFFFFFFFu, spp, o);
        stp += __shfl_down_sync(0xFFFFFFFFu, stp, o);
        st  += __shfl_down_sync(0xFFFFFFFFu, st, o);
    }

    __shared__ float4 sh[THREADS / 32];
    __shared__ bool   amLast;
    const int wid  = tid >> 5;
    const int lane = tid & 31;
    if (lane == 0) sh[wid] = make_float4(sp, spp, stp, st);
    __syncthreads();

    if (wid == 0) {
        float4 v = (lane < THREADS / 32) ? sh[lane] : make_float4(0.f, 0.f, 0.f, 0.f);
#pragma unroll
        for (int o = 4; o > 0; o >>= 1) {
            v.x += __shfl_down_sync(0xFFFFFFFFu, v.x, o);
            v.y += __shfl_down_sync(0xFFFFFFFFu, v.y, o);
            v.z += __shfl_down_sync(0xFFFFFFFFu, v.z, o);
            v.w += __shfl_down_sync(0xFFFFFFFFu, v.w, o);
        }
        if (lane == 0) {
            g_partials[blockIdx.x] = v;
            __threadfence();
            unsigned int prev = atomicAdd(&g_count, 1u);
            amLast = (prev == NBLOCKS - 1);
        }
    }
    __syncthreads();

    if (amLast) {
        __shared__ float dice[NB];
#pragma unroll
        for (int r = 0; r < 2; r++) {
            const int bb = wid * 2 + r;
            float fsp = 0.f, fspp = 0.f, fstp = 0.f, fst = 0.f;
            for (int j = lane; j < BPB; j += 32) {
                float4 a = __ldcg(&g_partials[bb * BPB + j]);
                fsp += a.x; fspp += a.y; fstp += a.z; fst += a.w;
            }
#pragma unroll
            for (int o = 16; o > 0; o >>= 1) {
                fsp  += __shfl_down_sync(0xFFFFFFFFu, fsp, o);
                fspp += __shfl_down_sync(0xFFFFFFFFu, fspp, o);
                fstp += __shfl_down_sync(0xFFFFFFFFu, fstp, o);
                fst  += __shfl_down_sync(0xFFFFFFFFu, fst, o);
            }
            if (lane == 0) {
                const float N = (float)HW;
                float num1 = 2.0f * fstp;
                float den1 = fspp + fst;
                float num0 = 2.0f * (N - fst - fsp + fstp);
                float den0 = (N - 2.0f * fsp + fspp) + (N - fst);
                dice[bb] = num1 / (den1 + EPS) + num0 / (den0 + EPS);
            }
        }
        __syncthreads();
        if (tid == 0) {
            float s = 0.f;
#pragma unroll
            for (int i = 0; i < NB; i++) s += dice[i];
            out[0] = 1.0f - s / (float)(2 * NB);
            g_count = 0;
        }
    }
}

extern "C" void kernel_launch(void* const* d_in, const int* in_sizes, int n_in,
                              void* d_out, int out_size) {
    const float* logits = (const float*)d_in[0];
    const int*   labels = (const int*)d_in[1];
    float*       out    = (float*)d_out;

    cudaFuncSetAttribute(dice_tma_kernel,
                         cudaFuncAttributeMaxDynamicSharedMemorySize, SMEM_TOTAL);
    dice_tma_kernel<<<NBLOCKS, THREADS, SMEM_TOTAL>>>(logits, labels, out);
}

// round 9
// speedup vs baseline: 1.0298x; 1.0298x over previous
#include <cuda_runtime.h>

#define HW (1024 * 1024)
#define NB 16
#define BLOCKS_PER_BATCH 64
#define NBLOCKS (NB * BLOCKS_PER_BATCH)   // 1024
#define THREADS 256
#define EPS 1e-6f

// per-batch running sums: {S_p, S_pp, S_tp, S_t}, accumulated via atomicAdd
__device__ float4 g_sums[NB];             // zero-initialized at load; reset by last block
__device__ unsigned int g_count = 0;      // self-resetting

__device__ __forceinline__ void accum(float l0, float l1, int t,
                                      float& sp, float& spp, float& stp, float& st) {
    // p1 = sigmoid(l1 - l0) = 1 / (1 + exp(l0 - l1))
    float e = __expf(l0 - l1);
    float p = __fdividef(1.0f, 1.0f + e);
    float tf = (t != 0) ? 1.0f : 0.0f;
    sp  += p;
    spp += p * p;
    stp += tf * p;
    st  += tf;
}

__global__ __launch_bounds__(THREADS, 8)
void dice_fused_kernel(const float* __restrict__ logits,
                       const int* __restrict__ labels,
                       float* __restrict__ out) {
    const int b   = blockIdx.x / BLOCKS_PER_BATCH;
    const int blk = blockIdx.x % BLOCKS_PER_BATCH;

    const float4* __restrict__ l0v = (const float4*)(logits + (size_t)b * 2 * HW);
    const float4* __restrict__ l1v = (const float4*)(logits + (size_t)b * 2 * HW + HW);
    const int4*   __restrict__ tv  = (const int4*)(labels + (size_t)b * HW);

    const int n4        = HW / 4;                  // 262144 float4 per plane
    const int per_block = n4 / BLOCKS_PER_BATCH;   // 4096
    const int base      = blk * per_block;

    float sp = 0.f, spp = 0.f, stp = 0.f, st = 0.f;

#pragma unroll 4
    for (int i = threadIdx.x; i < per_block; i += THREADS) {
        float4 a = l0v[base + i];
        float4 c = l1v[base + i];
        int4   t = tv[base + i];
        accum(a.x, c.x, t.x, sp, spp, stp, st);
        accum(a.y, c.y, t.y, sp, spp, stp, st);
        accum(a.z, c.z, t.z, sp, spp, stp, st);
        accum(a.w, c.w, t.w, sp, spp, stp, st);
    }

    // block reduce to one float4
#pragma unroll
    for (int o = 16; o > 0; o >>= 1) {
        sp  += __shfl_down_sync(0xFFFFFFFFu, sp, o);
        spp += __shfl_down_sync(0xFFFFFFFFu, spp, o);
        stp += __shfl_down_sync(0xFFFFFFFFu, stp, o);
        st  += __shfl_down_sync(0xFFFFFFFFu, st, o);
    }

    __shared__ float4 sh[THREADS / 32];
    __shared__ bool   amLast;
    const int wid  = threadIdx.x >> 5;
    const int lane = threadIdx.x & 31;
    if (lane == 0) sh[wid] = make_float4(sp, spp, stp, st);
    __syncthreads();

    if (wid == 0) {
        float4 v = (lane < THREADS / 32) ? sh[lane] : make_float4(0.f, 0.f, 0.f, 0.f);
#pragma unroll
        for (int o = 4; o > 0; o >>= 1) {
            v.x += __shfl_down_sync(0xFFFFFFFFu, v.x, o);
            v.y += __shfl_down_sync(0xFFFFFFFFu, v.y, o);
            v.z += __shfl_down_sync(0xFFFFFFFFu, v.z, o);
            v.w += __shfl_down_sync(0xFFFFFFFFu, v.w, o);
        }
        if (lane == 0) {
            float* dst = (float*)&g_sums[b];
            atomicAdd(dst + 0, v.x);
            atomicAdd(dst + 1, v.y);
            atomicAdd(dst + 2, v.z);
            atomicAdd(dst + 3, v.w);
            __threadfence();
            unsigned int prev = atomicAdd(&g_count, 1u);
            amLast = (prev == NBLOCKS - 1);
        }
    }
    __syncthreads();

    // ---- last block: tiny finish (one warp) ----
    if (amLast && wid == 0) {
        float dice = 0.f;
        if (lane < NB) {
            volatile float* vp = (volatile float*)&g_sums[lane];
            float vx = vp[0];
            float vy = vp[1];
            float vz = vp[2];
            float vw = vp[3];
            const float N = (float)HW;
            // channel 1
            float num1 = 2.0f * vz;
            float den1 = vy + vw;                 // S_pp + S_t (t^2 = t)
            // channel 0 (p0 = 1-p1, t0 = 1-t1)
            float num0 = 2.0f * (N - vw - vx + vz);
            float den0 = (N - 2.0f * vx + vy) + (N - vw);
            dice = num1 / (den1 + EPS) + num0 / (den0 + EPS);
        }
#pragma unroll
        for (int o = 16; o > 0; o >>= 1)
            dice += __shfl_down_sync(0xFFFFFFFFu, dice, o);
        if (lane == 0) {
            out[0] = 1.0f - dice / (float)(2 * NB);
        }
        // deterministic reset for next (graph-replayed) launch
        if (lane < NB) {
            g_sums[lane] = make_float4(0.f, 0.f, 0.f, 0.f);
        }
        if (lane == 0) g_count = 0;
    }
}

extern "C" void kernel_launch(void* const* d_in, const int* in_sizes, int n_in,
                              void* d_out, int out_size) {
    const float* logits = (const float*)d_in[0];
    const int*   labels = (const int*)d_in[1];
    float*       out    = (float*)d_out;

    dice_fused_kernel<<<NBLOCKS, THREADS>>>(logits, labels, out);
}